// round 1
// baseline (speedup 1.0000x reference)
#include <cuda_runtime.h>

#define FH 50
#define FW 50
#define CH 256
#define BATCH 4
#define NROI 1024
#define HOUT 7
#define WOUT 7
#define NBIN (HOUT*WOUT)
#define RATIO (1.0f/32.0f)

// Features transposed to BHWC so channel reads are contiguous.
__device__ float g_feats[BATCH * FH * FW * CH];

// ---------------------------------------------------------------------------
// Kernel 1: BCHW -> BHWC transpose. One block per (b, h) row; smem tile keeps
// both global read and global write coalesced.
// ---------------------------------------------------------------------------
__global__ void transpose_feats_kernel(const float* __restrict__ in) {
    __shared__ float tile[CH * FW];   // tile[c*FW + w]
    int b = blockIdx.x / FH;
    int h = blockIdx.x % FH;
    const float* src = in + (size_t)b * CH * FH * FW + (size_t)h * FW;
    for (int idx = threadIdx.x; idx < CH * FW; idx += blockDim.x) {
        int c = idx / FW, w = idx % FW;
        tile[idx] = src[(size_t)c * FH * FW + w];
    }
    __syncthreads();
    float* dst = g_feats + (size_t)(b * FH + h) * FW * CH;  // dst[w*CH + c]
    for (int idx = threadIdx.x; idx < FW * CH; idx += blockDim.x) {
        int w = idx / CH, c = idx % CH;
        dst[idx] = tile[c * FW + w];
    }
}

// ---------------------------------------------------------------------------
// Kernel 2: RoIAlign (max pool over 2x2 samples per bin).
// One block per roi, 128 threads = 128 float2 channel-pairs.
// Results staged in smem tile[c][k] (k = bin index), flushed coalesced.
// ---------------------------------------------------------------------------
__global__ void roialign_kernel(const float* __restrict__ rois,
                                float* __restrict__ out) {
    extern __shared__ float tile[];   // [CH][NBIN] : tile[c*NBIN + k]
    int r  = blockIdx.x;
    int c2 = threadIdx.x;             // channel pair index 0..127

    float fb  = __ldg(&rois[r * 5 + 0]);
    float bx1 = fminf(fmaxf(__ldg(&rois[r * 5 + 1]) * RATIO, 0.f), (float)FW);
    float by1 = fminf(fmaxf(__ldg(&rois[r * 5 + 2]) * RATIO, 0.f), (float)FH);
    float bx2 = fminf(fmaxf(__ldg(&rois[r * 5 + 3]) * RATIO, 0.f), (float)FW);
    float by2 = fminf(fmaxf(__ldg(&rois[r * 5 + 4]) * RATIO, 0.f), (float)FH);
    int  b = (int)fb;
    bool roi_valid = (bx2 - bx1 > 0.f) && (by2 - by1 > 0.f);
    float bin_w = (bx2 - bx1) * (1.0f / WOUT);
    float bin_h = (by2 - by1) * (1.0f / HOUT);

    const float2* fbase = (const float2*)g_feats + (size_t)b * FH * FW * (CH / 2);

    for (int i = 0; i < HOUT; i++) {
        float y1u = by1 + (float)i * bin_h;
        float y1b = fminf(fmaxf(y1u, 0.f), (float)FH);
        float y2b = fminf(fmaxf(y1u + bin_h, 0.f), (float)FH);
        int ylI[2], yhI[2];
        float wyb[2], wyt[2];
#pragma unroll
        for (int t = 0; t < 2; t++) {
            float py = y1b + ((float)t + 0.5f) * (bin_h * 0.5f);
            float yl = fminf(fmaxf(floorf(py), 0.f), (float)(FH - 1));
            ylI[t] = (int)yl;
            yhI[t] = min(ylI[t] + 1, FH - 1);
            wyb[t] = py - yl;                 // py - floor-clip(py)
            wyt[t] = (float)yhI[t] - py;      // NOT 1-wyb: matters at edges
        }
        for (int j = 0; j < WOUT; j++) {
            float x1u = bx1 + (float)j * bin_w;
            float x1b = fminf(fmaxf(x1u, 0.f), (float)FW);
            float x2b = fminf(fmaxf(x1u + bin_w, 0.f), (float)FW);
            int xlI[2], xhI[2];
            float wxl[2], wxh[2];
#pragma unroll
            for (int t = 0; t < 2; t++) {
                float px = x1b + ((float)t + 0.5f) * (bin_w * 0.5f);
                float xl = fminf(fmaxf(floorf(px), 0.f), (float)(FW - 1));
                xlI[t] = (int)xl;
                xhI[t] = min(xlI[t] + 1, FW - 1);
                wxh[t] = px - xl;
                wxl[t] = (float)xhI[t] - px;
            }
            bool valid = roi_valid && (x2b > x1b) && (y2b > y1b);

            float m0 = -3.402823466e38f, m1 = -3.402823466e38f;
#pragma unroll
            for (int ty = 0; ty < 2; ty++) {
                const float2* rowl = fbase + (size_t)(ylI[ty] * FW) * (CH / 2);
                const float2* rowh = fbase + (size_t)(yhI[ty] * FW) * (CH / 2);
#pragma unroll
                for (int tx = 0; tx < 2; tx++) {
                    float2 vtl = rowl[xlI[tx] * (CH / 2) + c2];
                    float2 vtr = rowl[xhI[tx] * (CH / 2) + c2];
                    float2 vbl = rowh[xlI[tx] * (CH / 2) + c2];
                    float2 vbr = rowh[xhI[tx] * (CH / 2) + c2];
                    float top0 = wxh[tx] * vtr.x + wxl[tx] * vtl.x;
                    float bot0 = wxh[tx] * vbr.x + wxl[tx] * vbl.x;
                    float v0   = wyb[ty] * bot0 + wyt[ty] * top0;
                    float top1 = wxh[tx] * vtr.y + wxl[tx] * vtl.y;
                    float bot1 = wxh[tx] * vbr.y + wxl[tx] * vbl.y;
                    float v1   = wyb[ty] * bot1 + wyt[ty] * top1;
                    m0 = fmaxf(m0, v0);
                    m1 = fmaxf(m1, v1);
                }
            }
            int k = i * WOUT + j;
            tile[(2 * c2 + 0) * NBIN + k] = valid ? m0 : 0.f;
            tile[(2 * c2 + 1) * NBIN + k] = valid ? m1 : 0.f;
        }
    }
    __syncthreads();
    // tile[c*49 + k] is exactly the output (N,C,7,7) order for this roi.
    float4* dst4       = (float4*)(out + (size_t)r * CH * NBIN);
    const float4* src4 = (const float4*)tile;
    for (int idx = threadIdx.x; idx < CH * NBIN / 4; idx += blockDim.x)
        dst4[idx] = src4[idx];
}

extern "C" void kernel_launch(void* const* d_in, const int* in_sizes, int n_in,
                              void* d_out, int out_size) {
    const float* feats = (const float*)d_in[0];   // (4,256,50,50) f32
    const float* rois  = (const float*)d_in[1];   // (1024,5) f32
    float* out = (float*)d_out;                   // (1024,256,7,7) f32

    const int smem_bytes = CH * NBIN * (int)sizeof(float);   // 50176 B
    cudaFuncSetAttribute(roialign_kernel,
                         cudaFuncAttributeMaxDynamicSharedMemorySize, smem_bytes);

    transpose_feats_kernel<<<BATCH * FH, 256>>>(feats);
    roialign_kernel<<<NROI, 128, smem_bytes>>>(rois, out);
}

// round 2
// speedup vs baseline: 1.4993x; 1.4993x over previous
#include <cuda_runtime.h>

#define FH 50
#define FW 50
#define CH 256
#define BATCH 4
#define NROI 1024
#define HOUT 7
#define WOUT 7
#define NBIN (HOUT*WOUT)
#define RATIO (1.0f/32.0f)
#define NGRP 4
#define TPB (128*NGRP)

// Features transposed to BHWC so channel reads are contiguous.
__device__ float g_feats[BATCH * FH * FW * CH];

// ---------------------------------------------------------------------------
// Kernel 1: BCHW -> BHWC transpose. One block per (b, h) row; smem tile keeps
// both global read and global write coalesced.
// ---------------------------------------------------------------------------
__global__ void transpose_feats_kernel(const float* __restrict__ in) {
    __shared__ float tile[CH * FW];   // tile[c*FW + w]
    int b = blockIdx.x / FH;
    int h = blockIdx.x % FH;
    const float* src = in + (size_t)b * CH * FH * FW + (size_t)h * FW;
    for (int idx = threadIdx.x; idx < CH * FW; idx += blockDim.x) {
        int c = idx / FW, w = idx % FW;
        tile[idx] = src[(size_t)c * FH * FW + w];
    }
    __syncthreads();
    float* dst = g_feats + (size_t)(b * FH + h) * FW * CH;  // dst[w*CH + c]
    for (int idx = threadIdx.x; idx < FW * CH; idx += blockDim.x) {
        int w = idx / CH, c = idx % CH;
        dst[idx] = tile[c * FW + w];
    }
}

// ---------------------------------------------------------------------------
// Kernel 2: RoIAlign (max over 2x2 samples per bin).
// One block per roi, 512 threads: tid&127 = channel pair, tid>>7 = bin group.
// Bin group g handles bins k = g, g+4, g+8, ... (49 bins over 4 groups).
// Results staged in smem tile[c][k], flushed coalesced as float4.
// ---------------------------------------------------------------------------
__global__ __launch_bounds__(TPB, 1)
void roialign_kernel(const float* __restrict__ rois,
                     float* __restrict__ out) {
    extern __shared__ float tile[];   // [CH][NBIN] : tile[c*NBIN + k]
    int r   = blockIdx.x;
    int c2  = threadIdx.x & 127;      // channel pair index 0..127
    int grp = threadIdx.x >> 7;       // bin group 0..3

    float fb  = __ldg(&rois[r * 5 + 0]);
    float bx1 = fminf(fmaxf(__ldg(&rois[r * 5 + 1]) * RATIO, 0.f), (float)FW);
    float by1 = fminf(fmaxf(__ldg(&rois[r * 5 + 2]) * RATIO, 0.f), (float)FH);
    float bx2 = fminf(fmaxf(__ldg(&rois[r * 5 + 3]) * RATIO, 0.f), (float)FW);
    float by2 = fminf(fmaxf(__ldg(&rois[r * 5 + 4]) * RATIO, 0.f), (float)FH);
    int  b = (int)fb;
    bool roi_valid = (bx2 - bx1 > 0.f) && (by2 - by1 > 0.f);
    float bin_w = (bx2 - bx1) * (1.0f / WOUT);
    float bin_h = (by2 - by1) * (1.0f / HOUT);

    const float2* fbase = (const float2*)g_feats + (size_t)b * FH * FW * (CH / 2);

    for (int k = grp; k < NBIN; k += NGRP) {
        int i = k / WOUT;
        int j = k - i * WOUT;

        float y1u = by1 + (float)i * bin_h;
        float y1b = fminf(fmaxf(y1u, 0.f), (float)FH);
        float y2b = fminf(fmaxf(y1u + bin_h, 0.f), (float)FH);
        float x1u = bx1 + (float)j * bin_w;
        float x1b = fminf(fmaxf(x1u, 0.f), (float)FW);
        float x2b = fminf(fmaxf(x1u + bin_w, 0.f), (float)FW);

        int ylI[2], yhI[2], xlI[2], xhI[2];
        float wyb[2], wyt[2], wxl[2], wxh[2];
#pragma unroll
        for (int t = 0; t < 2; t++) {
            float py = y1b + ((float)t + 0.5f) * (bin_h * 0.5f);
            float yl = fminf(fmaxf(floorf(py), 0.f), (float)(FH - 1));
            ylI[t] = (int)yl;
            yhI[t] = min(ylI[t] + 1, FH - 1);
            wyb[t] = py - yl;                 // py - floor-clip(py)
            wyt[t] = (float)yhI[t] - py;      // NOT 1-wyb: matters at edges

            float px = x1b + ((float)t + 0.5f) * (bin_w * 0.5f);
            float xl = fminf(fmaxf(floorf(px), 0.f), (float)(FW - 1));
            xlI[t] = (int)xl;
            xhI[t] = min(xlI[t] + 1, FW - 1);
            wxh[t] = px - xl;
            wxl[t] = (float)xhI[t] - px;
        }
        bool valid = roi_valid && (x2b > x1b) && (y2b > y1b);

        float m0 = -3.402823466e38f, m1 = -3.402823466e38f;
#pragma unroll
        for (int ty = 0; ty < 2; ty++) {
            const float2* rowl = fbase + (size_t)(ylI[ty] * FW) * (CH / 2);
            const float2* rowh = fbase + (size_t)(yhI[ty] * FW) * (CH / 2);
#pragma unroll
            for (int tx = 0; tx < 2; tx++) {
                float2 vtl = rowl[xlI[tx] * (CH / 2) + c2];
                float2 vtr = rowl[xhI[tx] * (CH / 2) + c2];
                float2 vbl = rowh[xlI[tx] * (CH / 2) + c2];
                float2 vbr = rowh[xhI[tx] * (CH / 2) + c2];
                float top0 = wxh[tx] * vtr.x + wxl[tx] * vtl.x;
                float bot0 = wxh[tx] * vbr.x + wxl[tx] * vbl.x;
                float v0   = wyb[ty] * bot0 + wyt[ty] * top0;
                float top1 = wxh[tx] * vtr.y + wxl[tx] * vtl.y;
                float bot1 = wxh[tx] * vbr.y + wxl[tx] * vbl.y;
                float v1   = wyb[ty] * bot1 + wyt[ty] * top1;
                m0 = fmaxf(m0, v0);
                m1 = fmaxf(m1, v1);
            }
        }
        tile[(2 * c2 + 0) * NBIN + k] = valid ? m0 : 0.f;
        tile[(2 * c2 + 1) * NBIN + k] = valid ? m1 : 0.f;
    }
    __syncthreads();
    // tile[c*49 + k] is exactly the output (N,C,7,7) order for this roi.
    float4* dst4       = (float4*)(out + (size_t)r * CH * NBIN);
    const float4* src4 = (const float4*)tile;
    for (int idx = threadIdx.x; idx < CH * NBIN / 4; idx += blockDim.x)
        dst4[idx] = src4[idx];
}

extern "C" void kernel_launch(void* const* d_in, const int* in_sizes, int n_in,
                              void* d_out, int out_size) {
    const float* feats = (const float*)d_in[0];   // (4,256,50,50) f32
    const float* rois  = (const float*)d_in[1];   // (1024,5) f32
    float* out = (float*)d_out;                   // (1024,256,7,7) f32

    const int smem_bytes = CH * NBIN * (int)sizeof(float);   // 50176 B
    cudaFuncSetAttribute(roialign_kernel,
                         cudaFuncAttributeMaxDynamicSharedMemorySize, smem_bytes);

    transpose_feats_kernel<<<BATCH * FH, 256>>>(feats);
    roialign_kernel<<<NROI, TPB, smem_bytes>>>(rois, out);
}

// round 3
// speedup vs baseline: 1.8558x; 1.2378x over previous
#include <cuda_runtime.h>

#define FH 50
#define FW 50
#define CH 256
#define BATCH 4
#define NROI 1024
#define HOUT 7
#define WOUT 7
#define NBIN (HOUT*WOUT)
#define RATIO (1.0f/32.0f)
#define NGRP 4
#define TPB (128*NGRP)

// smem layout: tile[CH*NBIN] then geometry table (17*NBIN words)
#define GEO_WORDS (17 * NBIN)
#define SMEM_FLOATS (CH * NBIN + GEO_WORDS)

// Features transposed to BHWC so channel reads are contiguous.
__device__ float g_feats[BATCH * FH * FW * CH];

// ---------------------------------------------------------------------------
// Kernel 1: BCHW -> BHWC transpose. One block per (b, h) row.
// ---------------------------------------------------------------------------
__global__ void transpose_feats_kernel(const float* __restrict__ in) {
    __shared__ float tile[CH * FW];   // tile[c*FW + w]
    int b = blockIdx.x / FH;
    int h = blockIdx.x % FH;
    const float* src = in + (size_t)b * CH * FH * FW + (size_t)h * FW;
    for (int idx = threadIdx.x; idx < CH * FW; idx += blockDim.x) {
        int c = idx / FW, w = idx % FW;
        tile[idx] = src[(size_t)c * FH * FW + w];
    }
    __syncthreads();
    float* dst = g_feats + (size_t)(b * FH + h) * FW * CH;  // dst[w*CH + c]
    for (int idx = threadIdx.x; idx < FW * CH; idx += blockDim.x) {
        int w = idx / CH, c = idx % CH;
        dst[idx] = tile[c * FW + w];
    }
}

// ---------------------------------------------------------------------------
// Kernel 2: RoIAlign. One block per roi, 512 threads.
//   Phase A: threads 0..48 compute per-bin geometry into smem once.
//   Phase B: tid&127 = channel pair, tid>>7 = bin group; pure loads + FMA.
//   Phase C: coalesced float4 flush of the staged (C,49) tile.
// ---------------------------------------------------------------------------
__global__ __launch_bounds__(TPB, 2)
void roialign_kernel(const float* __restrict__ rois,
                     float* __restrict__ out) {
    extern __shared__ float smem[];
    float* tile = smem;                           // [CH][NBIN]
    float* geo  = smem + CH * NBIN;
    int*   g_row = (int*)geo;                     // [4][NBIN]: yl0,yh0,yl1,yh1 (row offs, float2 units)
    int*   g_col = (int*)(geo + 4 * NBIN);        // [4][NBIN]: xl0,xh0,xl1,xh1 (col offs, float2 units)
    float* g_wy  = geo + 8 * NBIN;                // [4][NBIN]: wyb0,wyt0,wyb1,wyt1
    float* g_wx  = geo + 12 * NBIN;               // [4][NBIN]: wxh0,wxl0,wxh1,wxl1
    int*   g_val = (int*)(geo + 16 * NBIN);       // [NBIN]

    int r   = blockIdx.x;
    int tid = threadIdx.x;

    float fb = __ldg(&rois[r * 5 + 0]);
    int b = (int)fb;
    const float2* fbase = (const float2*)g_feats + (size_t)b * FH * FW * (CH / 2);

    // ---- Phase A: per-bin geometry (threads 0..48) ----
    if (tid < NBIN) {
        float bx1 = fminf(fmaxf(__ldg(&rois[r * 5 + 1]) * RATIO, 0.f), (float)FW);
        float by1 = fminf(fmaxf(__ldg(&rois[r * 5 + 2]) * RATIO, 0.f), (float)FH);
        float bx2 = fminf(fmaxf(__ldg(&rois[r * 5 + 3]) * RATIO, 0.f), (float)FW);
        float by2 = fminf(fmaxf(__ldg(&rois[r * 5 + 4]) * RATIO, 0.f), (float)FH);
        bool roi_valid = (bx2 - bx1 > 0.f) && (by2 - by1 > 0.f);
        float bin_w = (bx2 - bx1) * (1.0f / WOUT);
        float bin_h = (by2 - by1) * (1.0f / HOUT);

        int i = tid / WOUT;
        int j = tid - i * WOUT;

        float y1u = by1 + (float)i * bin_h;
        float y1b = fminf(fmaxf(y1u, 0.f), (float)FH);
        float y2b = fminf(fmaxf(y1u + bin_h, 0.f), (float)FH);
        float x1u = bx1 + (float)j * bin_w;
        float x1b = fminf(fmaxf(x1u, 0.f), (float)FW);
        float x2b = fminf(fmaxf(x1u + bin_w, 0.f), (float)FW);

#pragma unroll
        for (int t = 0; t < 2; t++) {
            float py = y1b + ((float)t + 0.5f) * (bin_h * 0.5f);
            float yl = fminf(fmaxf(floorf(py), 0.f), (float)(FH - 1));
            int ylI = (int)yl;
            int yhI = min(ylI + 1, FH - 1);
            g_row[(2 * t + 0) * NBIN + tid] = ylI * FW * (CH / 2);
            g_row[(2 * t + 1) * NBIN + tid] = yhI * FW * (CH / 2);
            g_wy[(2 * t + 0) * NBIN + tid] = py - yl;           // wyb
            g_wy[(2 * t + 1) * NBIN + tid] = (float)yhI - py;   // wyt (NOT 1-wyb)

            float px = x1b + ((float)t + 0.5f) * (bin_w * 0.5f);
            float xl = fminf(fmaxf(floorf(px), 0.f), (float)(FW - 1));
            int xlI = (int)xl;
            int xhI = min(xlI + 1, FW - 1);
            g_col[(2 * t + 0) * NBIN + tid] = xlI * (CH / 2);
            g_col[(2 * t + 1) * NBIN + tid] = xhI * (CH / 2);
            g_wx[(2 * t + 0) * NBIN + tid] = px - xl;           // wxh
            g_wx[(2 * t + 1) * NBIN + tid] = (float)xhI - px;   // wxl
        }
        g_val[tid] = (roi_valid && (x2b > x1b) && (y2b > y1b)) ? 1 : 0;
    }
    __syncthreads();

    // ---- Phase B: sampling. All lanes in a warp share k -> LDS broadcast ----
    int c2  = tid & 127;       // channel pair 0..127
    int grp = tid >> 7;        // bin group 0..3
    for (int k = grp; k < NBIN; k += NGRP) {
        float m0 = -3.402823466e38f, m1 = -3.402823466e38f;
#pragma unroll
        for (int ty = 0; ty < 2; ty++) {
            int rowl = g_row[(2 * ty + 0) * NBIN + k];
            int rowh = g_row[(2 * ty + 1) * NBIN + k];
            float wyb = g_wy[(2 * ty + 0) * NBIN + k];
            float wyt = g_wy[(2 * ty + 1) * NBIN + k];
#pragma unroll
            for (int tx = 0; tx < 2; tx++) {
                int coll = g_col[(2 * tx + 0) * NBIN + k];
                int colh = g_col[(2 * tx + 1) * NBIN + k];
                float wxh = g_wx[(2 * tx + 0) * NBIN + k];
                float wxl = g_wx[(2 * tx + 1) * NBIN + k];
                float2 vtl = fbase[rowl + coll + c2];
                float2 vtr = fbase[rowl + colh + c2];
                float2 vbl = fbase[rowh + coll + c2];
                float2 vbr = fbase[rowh + colh + c2];
                float top0 = wxh * vtr.x + wxl * vtl.x;
                float bot0 = wxh * vbr.x + wxl * vbl.x;
                float top1 = wxh * vtr.y + wxl * vtl.y;
                float bot1 = wxh * vbr.y + wxl * vbl.y;
                m0 = fmaxf(m0, wyb * bot0 + wyt * top0);
                m1 = fmaxf(m1, wyb * bot1 + wyt * top1);
            }
        }
        bool valid = g_val[k] != 0;
        tile[(2 * c2 + 0) * NBIN + k] = valid ? m0 : 0.f;
        tile[(2 * c2 + 1) * NBIN + k] = valid ? m1 : 0.f;
    }
    __syncthreads();

    // ---- Phase C: tile[c*49 + k] is exactly (N,C,7,7) order for this roi ----
    float4* dst4       = (float4*)(out + (size_t)r * CH * NBIN);
    const float4* src4 = (const float4*)tile;
    for (int idx = tid; idx < CH * NBIN / 4; idx += blockDim.x)
        dst4[idx] = src4[idx];
}

extern "C" void kernel_launch(void* const* d_in, const int* in_sizes, int n_in,
                              void* d_out, int out_size) {
    const float* feats = (const float*)d_in[0];   // (4,256,50,50) f32
    const float* rois  = (const float*)d_in[1];   // (1024,5) f32
    float* out = (float*)d_out;                   // (1024,256,7,7) f32

    const int smem_bytes = SMEM_FLOATS * (int)sizeof(float);  // ~53.5 KB
    cudaFuncSetAttribute(roialign_kernel,
                         cudaFuncAttributeMaxDynamicSharedMemorySize, smem_bytes);

    transpose_feats_kernel<<<BATCH * FH, 256>>>(feats);
    roialign_kernel<<<NROI, TPB, smem_bytes>>>(rois, out);
}

// round 4
// speedup vs baseline: 2.4044x; 1.2956x over previous
#include <cuda_runtime.h>

#define FH 50
#define FW 50
#define CH 256
#define BATCH 4
#define NROI 1024
#define HOUT 7
#define WOUT 7
#define NBIN (HOUT*WOUT)
#define RATIO (1.0f/32.0f)
#define NGRP 4
#define TPB (128*NGRP)

// smem: tile[CH*NBIN] floats (50176B, 16B-aligned) + 4 geo arrays of NBIN*16B
#define SMEM_BYTES (CH*NBIN*4 + 4*NBIN*16)

// Features transposed to BHWC so channel reads are contiguous.
__device__ float g_feats[BATCH * FH * FW * CH];

// ---------------------------------------------------------------------------
// Kernel 1: BCHW -> BHWC transpose. One block per (b, h) row.
// ---------------------------------------------------------------------------
__global__ void transpose_feats_kernel(const float* __restrict__ in) {
    __shared__ float tile[CH * FW];   // tile[c*FW + w]
    int b = blockIdx.x / FH;
    int h = blockIdx.x % FH;
    const float* src = in + (size_t)b * CH * FH * FW + (size_t)h * FW;
    for (int idx = threadIdx.x; idx < CH * FW; idx += blockDim.x) {
        int c = idx / FW, w = idx % FW;
        tile[idx] = src[(size_t)c * FH * FW + w];
    }
    __syncthreads();
    float* dst = g_feats + (size_t)(b * FH + h) * FW * CH;  // dst[w*CH + c]
    for (int idx = threadIdx.x; idx < FW * CH; idx += blockDim.x) {
        int w = idx / CH, c = idx % CH;
        dst[idx] = tile[c * FW + w];
    }
}

// bilinear + max for one sample (float2 = 2 channels)
#define SAMPLE(m0, m1, q00, q01, q10, q11, xh, xl, yb, yt)          \
    do {                                                            \
        float top0 = (xh) * (q01).x + (xl) * (q00).x;               \
        float bot0 = (xh) * (q11).x + (xl) * (q10).x;               \
        float top1 = (xh) * (q01).y + (xl) * (q00).y;               \
        float bot1 = (xh) * (q11).y + (xl) * (q10).y;               \
        m0 = fmaxf(m0, (yb) * bot0 + (yt) * top0);                  \
        m1 = fmaxf(m1, (yb) * bot1 + (yt) * top1);                  \
    } while (0)

// ---------------------------------------------------------------------------
// Kernel 2: RoIAlign. One block per roi, 512 threads.
//   Phase A: threads 0..48 build per-bin geometry (4 x 16B vectors per bin).
//            Invalid bins get zeroed y-weights -> sample values are exactly 0.
//   Phase B: tid&127 = channel pair, tid>>7 = bin group. Corner-sets are
//            deduped via warp-uniform branches (samples usually share cells).
//   Phase C: coalesced float4 flush of the staged (C,49) tile.
// ---------------------------------------------------------------------------
__global__ __launch_bounds__(TPB, 2)
void roialign_kernel(const float* __restrict__ rois,
                     float* __restrict__ out) {
    extern __shared__ float smem[];
    float*  tile   = smem;                              // [CH][NBIN]
    int4*   g_rows = (int4*)(smem + CH * NBIN);         // [NBIN] yl0,yh0,yl1,yh1 (row offs, float2 units)
    int4*   g_cols = g_rows + NBIN;                     // [NBIN] xl0,xh0,xl1,xh1 (col offs, float2 units)
    float4* g_wy   = (float4*)(g_cols + NBIN);          // [NBIN] wyb0,wyt0,wyb1,wyt1 (0 if invalid)
    float4* g_wx   = g_wy + NBIN;                       // [NBIN] wxh0,wxl0,wxh1,wxl1

    int r   = blockIdx.x;
    int tid = threadIdx.x;

    int b = (int)__ldg(&rois[r * 5 + 0]);
    const float2* fbase = (const float2*)g_feats + (size_t)b * FH * FW * (CH / 2);

    // ---- Phase A ----
    if (tid < NBIN) {
        float bx1 = fminf(fmaxf(__ldg(&rois[r * 5 + 1]) * RATIO, 0.f), (float)FW);
        float by1 = fminf(fmaxf(__ldg(&rois[r * 5 + 2]) * RATIO, 0.f), (float)FH);
        float bx2 = fminf(fmaxf(__ldg(&rois[r * 5 + 3]) * RATIO, 0.f), (float)FW);
        float by2 = fminf(fmaxf(__ldg(&rois[r * 5 + 4]) * RATIO, 0.f), (float)FH);
        bool roi_valid = (bx2 - bx1 > 0.f) && (by2 - by1 > 0.f);
        float bin_w = (bx2 - bx1) * (1.0f / WOUT);
        float bin_h = (by2 - by1) * (1.0f / HOUT);

        int i = tid / WOUT;
        int j = tid - i * WOUT;

        float y1u = by1 + (float)i * bin_h;
        float y1b = fminf(fmaxf(y1u, 0.f), (float)FH);
        float y2b = fminf(fmaxf(y1u + bin_h, 0.f), (float)FH);
        float x1u = bx1 + (float)j * bin_w;
        float x1b = fminf(fmaxf(x1u, 0.f), (float)FW);
        float x2b = fminf(fmaxf(x1u + bin_w, 0.f), (float)FW);
        bool valid = roi_valid && (x2b > x1b) && (y2b > y1b);
        float vscale = valid ? 1.f : 0.f;

        int   rowi[4], coli[4];
        float wyv[4], wxv[4];
#pragma unroll
        for (int t = 0; t < 2; t++) {
            float py = y1b + ((float)t + 0.5f) * (bin_h * 0.5f);
            float yl = fminf(fmaxf(floorf(py), 0.f), (float)(FH - 1));
            int ylI = (int)yl;
            int yhI = min(ylI + 1, FH - 1);
            rowi[2 * t + 0] = ylI * FW * (CH / 2);
            rowi[2 * t + 1] = yhI * FW * (CH / 2);
            wyv[2 * t + 0] = (py - yl) * vscale;          // wyb (zeroed if invalid)
            wyv[2 * t + 1] = ((float)yhI - py) * vscale;  // wyt (NOT 1-wyb)

            float px = x1b + ((float)t + 0.5f) * (bin_w * 0.5f);
            float xl = fminf(fmaxf(floorf(px), 0.f), (float)(FW - 1));
            int xlI = (int)xl;
            int xhI = min(xlI + 1, FW - 1);
            coli[2 * t + 0] = xlI * (CH / 2);
            coli[2 * t + 1] = xhI * (CH / 2);
            wxv[2 * t + 0] = px - xl;          // wxh
            wxv[2 * t + 1] = (float)xhI - px;  // wxl
        }
        g_rows[tid] = make_int4(rowi[0], rowi[1], rowi[2], rowi[3]);
        g_cols[tid] = make_int4(coli[0], coli[1], coli[2], coli[3]);
        g_wy[tid]   = make_float4(wyv[0], wyv[1], wyv[2], wyv[3]);
        g_wx[tid]   = make_float4(wxv[0], wxv[1], wxv[2], wxv[3]);
    }
    __syncthreads();

    // ---- Phase B ----
    int c2  = tid & 127;       // channel pair 0..127
    int grp = tid >> 7;        // bin group 0..3
    const float2* fb2 = fbase + c2;

    for (int k = grp; k < NBIN; k += NGRP) {
        int4   rw = g_rows[k];
        int4   cl = g_cols[k];
        float4 wy = g_wy[k];
        float4 wx = g_wx[k];
        bool sameX = (cl.z == cl.x) && (cl.w == cl.y);
        bool sameY = (rw.z == rw.x) && (rw.w == rw.y);

        // Corner set A: rows pair0 x cols pair0 (always needed)
        float2 a00 = fb2[rw.x + cl.x];
        float2 a01 = fb2[rw.x + cl.y];
        float2 a10 = fb2[rw.y + cl.x];
        float2 a11 = fb2[rw.y + cl.y];

        float v0 = wx.x * a01.x + wx.y * a00.x;   // sample(0,0) top
        float w0 = wx.x * a11.x + wx.y * a10.x;   // bot
        float v1 = wx.x * a01.y + wx.y * a00.y;
        float w1 = wx.x * a11.y + wx.y * a10.y;
        float m0 = wy.x * w0 + wy.y * v0;
        float m1 = wy.x * w1 + wy.y * v1;

        // Corner set B: rows pair0 x cols pair1
        float2 b00, b01, b10, b11;
        if (sameX) { b00 = a00; b01 = a01; b10 = a10; b11 = a11; }
        else {
            b00 = fb2[rw.x + cl.z]; b01 = fb2[rw.x + cl.w];
            b10 = fb2[rw.y + cl.z]; b11 = fb2[rw.y + cl.w];
        }
        SAMPLE(m0, m1, b00, b01, b10, b11, wx.z, wx.w, wy.x, wy.y);

        // Corner sets C (rows pair1 x cols pair0) and D (rows pair1 x cols pair1)
        float2 c00, c01, c10, c11, d00, d01, d10, d11;
        if (sameY) {
            c00 = a00; c01 = a01; c10 = a10; c11 = a11;
            d00 = b00; d01 = b01; d10 = b10; d11 = b11;
        } else {
            c00 = fb2[rw.z + cl.x]; c01 = fb2[rw.z + cl.y];
            c10 = fb2[rw.w + cl.x]; c11 = fb2[rw.w + cl.y];
            if (sameX) { d00 = c00; d01 = c01; d10 = c10; d11 = c11; }
            else {
                d00 = fb2[rw.z + cl.z]; d01 = fb2[rw.z + cl.w];
                d10 = fb2[rw.w + cl.z]; d11 = fb2[rw.w + cl.w];
            }
        }
        SAMPLE(m0, m1, c00, c01, c10, c11, wx.x, wx.y, wy.z, wy.w);
        SAMPLE(m0, m1, d00, d01, d10, d11, wx.z, wx.w, wy.z, wy.w);

        tile[(2 * c2 + 0) * NBIN + k] = m0;
        tile[(2 * c2 + 1) * NBIN + k] = m1;
    }
    __syncthreads();

    // ---- Phase C: tile[c*49 + k] is exactly (N,C,7,7) order for this roi ----
    float4* dst4       = (float4*)(out + (size_t)r * CH * NBIN);
    const float4* src4 = (const float4*)tile;
    for (int idx = tid; idx < CH * NBIN / 4; idx += blockDim.x)
        dst4[idx] = src4[idx];
}

extern "C" void kernel_launch(void* const* d_in, const int* in_sizes, int n_in,
                              void* d_out, int out_size) {
    const float* feats = (const float*)d_in[0];   // (4,256,50,50) f32
    const float* rois  = (const float*)d_in[1];   // (1024,5) f32
    float* out = (float*)d_out;                   // (1024,256,7,7) f32

    cudaFuncSetAttribute(roialign_kernel,
                         cudaFuncAttributeMaxDynamicSharedMemorySize, SMEM_BYTES);

    transpose_feats_kernel<<<BATCH * FH, 512>>>(feats);
    roialign_kernel<<<NROI, TPB, SMEM_BYTES>>>(rois, out);
}